// round 12
// baseline (speedup 1.0000x reference)
#include <cuda_runtime.h>

// Problem constants
#define HID     50
#define NG      200
#define IN0     17
#define SDIM    16
#define TSTEPS  128
#define FC1N    25

// Tiling: two independent 32-row halves, 13 warps each; half B phase-rotated
#define ROWS      64
#define HROWS     32
#define NTHREADS  832
#define HTHREADS  416

// Strides
#define FC1_S     51
#define TSTRIDE   68      // floats; 272B rows, 16B-aligned
#define W4I_S     17      // wih0 float4 stride per j
#define W4H_S     51      // hh float4 stride per j

typedef unsigned long long ull;

__device__ __forceinline__ ull pack2(float a, float b) {
    ull r; asm("mov.b64 %0,{%1,%2};" : "=l"(r) : "f"(a), "f"(b)); return r;
}
__device__ __forceinline__ float2 unpk(ull v) {
    float2 f; asm("mov.b64 {%0,%1},%2;" : "=f"(f.x), "=f"(f.y) : "l"(v)); return f;
}
__device__ __forceinline__ void fma2(ull& d, ull a, ull b) {
    asm("fma.rn.f32x2 %0,%1,%2,%0;" : "+l"(d) : "l"(a), "l"(b));
}
__device__ __forceinline__ void add2(ull& d, ull a) {
    asm("add.rn.f32x2 %0,%0,%1;" : "+l"(d) : "l"(a));
}
__device__ __forceinline__ float tanh_a(float x) {
    float y; asm("tanh.approx.f32 %0,%1;" : "=f"(y) : "f"(x)); return y;
}
__device__ __forceinline__ float sig_a(float x) {
    return fmaf(tanh_a(0.5f * x), 0.5f, 0.5f);
}
__device__ __forceinline__ void half_bar(int half) {
    asm volatile("bar.sync %0, %1;" :: "r"(half + 1), "r"(HTHREADS) : "memory");
}

// Shared layout (float offsets; float4 regions 16B aligned)
#define OFF_W4_IH0 0         // 3400
#define OFF_W4_HH0 3400      // 10200
#define OFF_W4_IH1 13600     // 10200
#define OFF_W4_HH1 23800     // 10200
#define OFF_FC1    34000     // 1275
#define OFF_FC2    35276     // 25
#define OFF_B0     35302     // 200
#define OFF_B1     35502     // 200
#define OFF_BFC1   35702     // 25
#define OFF_BFC2   35728     // 2 (+2 pad)
#define OFF_X      35732     // 17*68 = 1156
#define OFF_H0     36888     // 2*50*68 = 6800
#define OFF_H1     43688     // 6800
#define SMEM_FLOATS 50488    // 201952 bytes

// One k of gate MACs: float4 weights (4 gates), one LDS.128 of state (4 rows)
#define GATEK(PW, SBASE, K) do { \
    float4 wv_ = (PW)[K]; \
    ull wi_ = pack2(wv_.x, wv_.x), wf_ = pack2(wv_.y, wv_.y); \
    ull wg_ = pack2(wv_.z, wv_.z), wo_ = pack2(wv_.w, wv_.w); \
    ulonglong2 sv_ = *(const ulonglong2*)((SBASE) + (K) * TSTRIDE); \
    fma2(ai[0], wi_, sv_.x); fma2(ai[1], wi_, sv_.y); \
    fma2(af[0], wf_, sv_.x); fma2(af[1], wf_, sv_.y); \
    fma2(ag[0], wg_, sv_.x); fma2(ag[1], wg_, sv_.y); \
    fma2(ao[0], wo_, sv_.x); fma2(ao[1], wo_, sv_.y); \
} while (0)

__global__ __launch_bounds__(NTHREADS, 1)
void kozyra_lstm_kernel(const float* __restrict__ features,
                        const float* __restrict__ w_ih0, const float* __restrict__ w_hh0,
                        const float* __restrict__ b0,
                        const float* __restrict__ w_ih1, const float* __restrict__ w_hh1,
                        const float* __restrict__ b1,
                        const float* __restrict__ w_fc1, const float* __restrict__ b_fc1,
                        const float* __restrict__ w_fc2, const float* __restrict__ b_fc2,
                        float* __restrict__ out)
{
    extern __shared__ float sm[];
    float* s_fc1  = sm + OFF_FC1;
    float* s_fc2  = sm + OFF_FC2;
    float* s_b0   = sm + OFF_B0;
    float* s_b1   = sm + OFF_B1;
    float* s_bfc1 = sm + OFF_BFC1;
    float* s_bfc2 = sm + OFF_BFC2;
    float* s_x    = sm + OFF_X;      // [IN0][TSTRIDE], row 16 = delta
    float* s_h0b  = sm + OFF_H0;     // 2 x [HID][TSTRIDE]
    float* s_h1b  = sm + OFF_H1;

    const int tid  = threadIdx.x;
    const int brow = blockIdx.x * ROWS;

    // ---- Stage weights interleaved as float4 (wi,wf,wg,wo) per (j,k) ----
    for (int i = tid; i < HID * IN0 * 4; i += NTHREADS) {
        int gate = i & 3, rest = i >> 2;
        int jj = rest / IN0, k = rest % IN0;
        sm[OFF_W4_IH0 + (jj * W4I_S + k) * 4 + gate] = w_ih0[(gate * HID + jj) * IN0 + k];
    }
    for (int i = tid; i < HID * W4H_S * 4; i += NTHREADS) {
        int gate = i & 3, rest = i >> 2;
        int jj = rest / W4H_S, k = rest % W4H_S;
        float v0 = 0.0f, v1 = 0.0f, v2 = 0.0f;
        if (k < HID) {
            int src = (gate * HID + jj) * HID + k;
            v0 = w_hh0[src]; v1 = w_ih1[src]; v2 = w_hh1[src];
        }
        int o = (jj * W4H_S + k) * 4 + gate;
        sm[OFF_W4_HH0 + o] = v0;
        sm[OFF_W4_IH1 + o] = v1;
        sm[OFF_W4_HH1 + o] = v2;
    }
    for (int i = tid; i < FC1N * HID; i += NTHREADS) {
        int n = i / HID, k = i % HID;
        s_fc1[n * FC1_S + k] = w_fc1[i];
    }
    for (int i = tid; i < FC1N; i += NTHREADS) { s_fc2[i] = w_fc2[i]; s_bfc1[i] = b_fc1[i]; }
    for (int i = tid; i < NG;   i += NTHREADS) { s_b0[i] = b0[i]; s_b1[i] = b1[i]; }
    if (tid == 0) s_bfc2[0] = b_fc2[0];

    // ---- Init state + x for t=0 ----
    for (int i = tid; i < 2 * HID * TSTRIDE; i += NTHREADS) { s_h0b[i] = 0.0f; s_h1b[i] = 0.0f; }
    const float* fbase = features + (size_t)brow * (TSTEPS * SDIM);
    for (int i = tid; i < ROWS * SDIM; i += NTHREADS) {
        int r = i >> 4, s = i & 15;
        s_x[s * TSTRIDE + r] = fbase[(size_t)r * (TSTEPS * SDIM) + s];
    }
    if (tid < ROWS) s_x[SDIM * TSTRIDE + tid] = 0.0f;
    __syncthreads();   // last full-block barrier

    // ---- Thread mapping: half (13 warps, 32 rows); gs selects a 4-row subgroup ----
    const int w    = tid >> 5;
    const int lane = tid & 31;
    const int half = (w >= 13) ? 1 : 0;
    const int hw   = w - half * 13;
    const int gs   = lane >> 4;
    const int sub  = lane & 15;
    int rg, j; bool dup = false;
    if (hw < 12) { rg = hw / 3; j = (hw % 3) * 16 + sub; }
    else { j = 48 + (sub & 1); rg = (sub >> 1) & 3; dup = (sub >= 8); }
    const int hbase = half * HROWS;
    const int r0 = hbase + rg * 8 + gs * 4;   // this thread's 4 rows

    const float4* pW_ih0 = (const float4*)(sm + OFF_W4_IH0) + j * W4I_S;
    const float4* pW_hh0 = (const float4*)(sm + OFF_W4_HH0) + j * W4H_S;
    const float4* pW_ih1 = (const float4*)(sm + OFF_W4_IH1) + j * W4H_S;
    const float4* pW_hh1 = (const float4*)(sm + OFF_W4_HH1) + j * W4H_S;

    const ull bi0 = pack2(s_b0[j], s_b0[j]);
    const ull bf0 = pack2(s_b0[HID + j], s_b0[HID + j]);
    const ull bg0 = pack2(s_b0[2*HID + j], s_b0[2*HID + j]);
    const ull bo0 = pack2(s_b0[3*HID + j], s_b0[3*HID + j]);
    const ull bi1 = pack2(s_b1[j], s_b1[j]);
    const ull bf1 = pack2(s_b1[HID + j], s_b1[HID + j]);
    const ull bg1 = pack2(s_b1[2*HID + j], s_b1[2*HID + j]);
    const ull bo1 = pack2(s_b1[3*HID + j], s_b1[3*HID + j]);

    float cx[2][2], cy[2][2];
    cx[0][0]=cx[0][1]=cy[0][0]=cy[0][1]=0.0f;
    cx[1][0]=cx[1][1]=cy[1][0]=cy[1][1]=0.0f;

    // ---- Phase bodies as lambdas (inlined) ----

    // P1: layer-0 gates + epilogue(0)
    auto P1 = [&](int t) {
        const int pb = t & 1;
        const float* h0r = s_h0b + pb * (HID * TSTRIDE);
        float* h0w = s_h0b + (pb ^ 1) * (HID * TSTRIDE);
        ull ai[2], af[2], ag[2], ao[2];
        ai[0]=ai[1]=bi0; af[0]=af[1]=bf0; ag[0]=ag[1]=bg0; ao[0]=ao[1]=bo0;
        {
            const float* sx = &s_x[r0];
            #pragma unroll
            for (int k = 0; k < IN0; k++) GATEK(pW_ih0, sx, k);
        }
        {
            const float* sh = &h0r[r0];
            #pragma unroll 5
            for (int k = 0; k < HID; k++) GATEK(pW_hh0, sh, k);
        }
        float hv[4];
        #pragma unroll
        for (int p = 0; p < 2; p++) {
            float2 vi = unpk(ai[p]), vf = unpk(af[p]), vg = unpk(ag[p]), vo = unpk(ao[p]);
            float ncx = sig_a(vf.x) * cx[0][p] + sig_a(vi.x) * tanh_a(vg.x);
            float ncy = sig_a(vf.y) * cy[0][p] + sig_a(vi.y) * tanh_a(vg.y);
            cx[0][p] = ncx; cy[0][p] = ncy;
            hv[2*p]     = sig_a(vo.x) * tanh_a(ncx);
            hv[2*p + 1] = sig_a(vo.y) * tanh_a(ncy);
        }
        if (!dup) {
            float4 q; q.x = hv[0]; q.y = hv[1]; q.z = hv[2]; q.w = hv[3];
            *(float4*)&h0w[j * TSTRIDE + r0] = q;
        }
    };

    // P2: layer-1 gates + epilogue(1)
    auto P2 = [&](int t) {
        const int pb = t & 1;
        float* h0w = s_h0b + (pb ^ 1) * (HID * TSTRIDE);
        const float* h1r = s_h1b + pb * (HID * TSTRIDE);
        float* h1w = s_h1b + (pb ^ 1) * (HID * TSTRIDE);
        ull ai[2], af[2], ag[2], ao[2];
        ai[0]=ai[1]=bi1; af[0]=af[1]=bf1; ag[0]=ag[1]=bg1; ao[0]=ao[1]=bo1;
        {
            const float* sh = &h0w[r0];
            #pragma unroll 5
            for (int k = 0; k < HID; k++) GATEK(pW_ih1, sh, k);
        }
        {
            const float* sh = &h1r[r0];
            #pragma unroll 5
            for (int k = 0; k < HID; k++) GATEK(pW_hh1, sh, k);
        }
        float hv[4];
        #pragma unroll
        for (int p = 0; p < 2; p++) {
            float2 vi = unpk(ai[p]), vf = unpk(af[p]), vg = unpk(ag[p]), vo = unpk(ao[p]);
            float ncx = sig_a(vf.x) * cx[1][p] + sig_a(vi.x) * tanh_a(vg.x);
            float ncy = sig_a(vf.y) * cy[1][p] + sig_a(vi.y) * tanh_a(vg.y);
            cx[1][p] = ncx; cy[1][p] = ncy;
            hv[2*p]     = sig_a(vo.x) * tanh_a(ncx);
            hv[2*p + 1] = sig_a(vo.y) * tanh_a(ncy);
        }
        if (!dup) {
            float4 q; q.x = hv[0]; q.y = hv[1]; q.z = hv[2]; q.w = hv[3];
            *(float4*)&h1w[j * TSTRIDE + r0] = q;
        }
    };

    // P3: fused fc1+fc2 (warps 0-7 of the half) + feature staging for t+1
    auto P3 = [&](int t) {
        const int pb = t & 1;
        float* h1w = s_h1b + (pb ^ 1) * (HID * TSTRIDE);
        const bool has_next = (t + 1 < TSTEPS);

        int hidx = hw * 32 + lane;
        float f0 = 0.0f, f1 = 0.0f;
        int rA = hidx >> 4, sA = hidx & 15;
        int hidx2 = hidx + HTHREADS;
        int rB = hidx2 >> 4, sB = hidx2 & 15;
        if (has_next) {
            f0 = fbase[(size_t)(hbase + rA) * (TSTEPS * SDIM) + (size_t)(t + 1) * SDIM + sA];
            if (rB < HROWS)
                f1 = fbase[(size_t)(hbase + rB) * (TSTEPS * SDIM) + (size_t)(t + 1) * SDIM + sB];
        }

        if (hw < 8) {
            int rb = hbase + hw * 4;
            ull acc0 = 0ULL, acc1 = 0ULL;
            if (lane < FC1N) {
                float bb1 = s_bfc1[lane];
                acc0 = pack2(bb1, bb1); acc1 = acc0;
                const float* wr = &s_fc1[lane * FC1_S];
                #pragma unroll 10
                for (int k = 0; k < HID; k++) {
                    float wv = wr[k];
                    ull wp = pack2(wv, wv);
                    ulonglong2 hv = *(const ulonglong2*)&h1w[k * TSTRIDE + rb];
                    fma2(acc0, wp, hv.x);
                    fma2(acc1, wp, hv.y);
                }
                float2 u0 = unpk(acc0), u1 = unpk(acc1);
                float sc = s_fc2[lane];
                u0.x = fmaxf(u0.x, 0.0f) * sc;  u0.y = fmaxf(u0.y, 0.0f) * sc;
                u1.x = fmaxf(u1.x, 0.0f) * sc;  u1.y = fmaxf(u1.y, 0.0f) * sc;
                acc0 = pack2(u0.x, u0.y); acc1 = pack2(u1.x, u1.y);
            }
            #pragma unroll
            for (int off = 16; off > 0; off >>= 1) {
                add2(acc0, __shfl_down_sync(0xffffffffu, acc0, off));
                add2(acc1, __shfl_down_sync(0xffffffffu, acc1, off));
            }
            if (lane == 0) {
                float2 d0 = unpk(acc0), d1 = unpk(acc1);
                float bb = s_bfc2[0];
                d0.x += bb; d0.y += bb; d1.x += bb; d1.y += bb;
                float4 dd; dd.x = d0.x; dd.y = d0.y; dd.z = d1.x; dd.w = d1.y;
                *(float4*)&s_x[SDIM * TSTRIDE + rb] = dd;   // delta -> next x
                out[(size_t)(brow + rb)     * TSTEPS + t] = d0.x;
                out[(size_t)(brow + rb + 1) * TSTEPS + t] = d0.y;
                out[(size_t)(brow + rb + 2) * TSTEPS + t] = d1.x;
                out[(size_t)(brow + rb + 3) * TSTEPS + t] = d1.y;
            }
        }

        if (has_next) {
            s_x[sA * TSTRIDE + hbase + rA] = f0;
            if (rB < HROWS)
                s_x[sB * TSTRIDE + hbase + rB] = f1;
        }
    };

    // ---- Main loop: half A in phase order, half B rotated by one phase ----
    if (half == 0) {
        for (int t = 0; t < TSTEPS; t++) {
            P1(t); half_bar(0);
            P2(t); half_bar(0);
            P3(t); half_bar(0);
        }
    } else {
        P1(0); half_bar(1);
        for (int t = 0; t < TSTEPS; t++) {
            P2(t); half_bar(1);
            P3(t); half_bar(1);
            if (t + 1 < TSTEPS) { P1(t + 1); half_bar(1); }
        }
    }
}

extern "C" void kernel_launch(void* const* d_in, const int* in_sizes, int n_in,
                              void* d_out, int out_size)
{
    const float* features = (const float*)d_in[0];
    const float* w_ih0    = (const float*)d_in[1];
    const float* w_hh0    = (const float*)d_in[2];
    const float* b0       = (const float*)d_in[3];
    const float* w_ih1    = (const float*)d_in[4];
    const float* w_hh1    = (const float*)d_in[5];
    const float* b1       = (const float*)d_in[6];
    const float* w_fc1    = (const float*)d_in[7];
    const float* b_fc1    = (const float*)d_in[8];
    const float* w_fc2    = (const float*)d_in[9];
    const float* b_fc2    = (const float*)d_in[10];
    float* out = (float*)d_out;

    const int batch = in_sizes[0] / (TSTEPS * SDIM);
    const int nblocks = batch / ROWS;

    const size_t smem_bytes = SMEM_FLOATS * sizeof(float);
    cudaFuncSetAttribute(kozyra_lstm_kernel,
                         cudaFuncAttributeMaxDynamicSharedMemorySize,
                         (int)smem_bytes);

    kozyra_lstm_kernel<<<nblocks, NTHREADS, smem_bytes>>>(
        features, w_ih0, w_hh0, b0, w_ih1, w_hh1, b1,
        w_fc1, b_fc1, w_fc2, b_fc2, out);
}

// round 13
// speedup vs baseline: 1.6006x; 1.6006x over previous
#include <cuda_runtime.h>

// Problem constants
#define HID     50
#define NG      200
#define IN0     17
#define SDIM    16
#define TSTEPS  128
#define FC1N    25

// Tiling: two independent 32-row halves, 13 warps each (R10 structure)
#define ROWS      64
#define HROWS     32
#define NTHREADS  832
#define HTHREADS  416

// Strides
#define FC1_S     51
#define TSTRIDE   68      // floats; 272B rows, 16B-aligned
#define W4I_S     17      // wih0 float4 stride per j
#define W4H_S     51      // hh float4 stride per j
#define KSPLIT    20      // hh0 k's done in Ph2; rest in Ph3

typedef unsigned long long ull;

__device__ __forceinline__ ull pack2(float a, float b) {
    ull r; asm("mov.b64 %0,{%1,%2};" : "=l"(r) : "f"(a), "f"(b)); return r;
}
__device__ __forceinline__ float2 unpk(ull v) {
    float2 f; asm("mov.b64 {%0,%1},%2;" : "=f"(f.x), "=f"(f.y) : "l"(v)); return f;
}
__device__ __forceinline__ void fma2(ull& d, ull a, ull b) {
    asm("fma.rn.f32x2 %0,%1,%2,%0;" : "+l"(d) : "l"(a), "l"(b));
}
__device__ __forceinline__ void add2(ull& d, ull a) {
    asm("add.rn.f32x2 %0,%0,%1;" : "+l"(d) : "l"(a));
}
__device__ __forceinline__ float tanh_a(float x) {
    float y; asm("tanh.approx.f32 %0,%1;" : "=f"(y) : "f"(x)); return y;
}
__device__ __forceinline__ float sig_a(float x) {
    return fmaf(tanh_a(0.5f * x), 0.5f, 0.5f);
}
__device__ __forceinline__ void half_bar(int half) {
    asm volatile("bar.sync %0, %1;" :: "r"(half + 1), "r"(HTHREADS) : "memory");
}

// Shared layout (float offsets; float4 regions 16B aligned)
#define OFF_W4_IH0 0         // 3400
#define OFF_W4_HH0 3400      // 10200
#define OFF_W4_IH1 13600     // 10200
#define OFF_W4_HH1 23800     // 10200
#define OFF_FC1    34000     // 1275
#define OFF_FC2    35276     // 25
#define OFF_BFC1   35302     // 25
#define OFF_BFC2   35328     // 2 (+2 pad)
#define OFF_B0Q    35332     // 200 (float4 per j: i,f,g,o)
#define OFF_B1Q    35532     // 200
#define OFF_X      35732     // 17*68 = 1156, row 16 = delta
#define OFF_H0     36888     // 2*50*68 = 6800
#define OFF_H1     43688     // 6800
#define SMEM_FLOATS 50488    // 201952 bytes

// One k of gate MACs: float4 weights (4 gates), one LDS.128 of state (4 rows)
#define GATEK(PW, SBASE, K) do { \
    float4 wv_ = (PW)[K]; \
    ull wi_ = pack2(wv_.x, wv_.x), wf_ = pack2(wv_.y, wv_.y); \
    ull wg_ = pack2(wv_.z, wv_.z), wo_ = pack2(wv_.w, wv_.w); \
    ulonglong2 sv_ = *(const ulonglong2*)((SBASE) + (K) * TSTRIDE); \
    fma2(ai[0], wi_, sv_.x); fma2(ai[1], wi_, sv_.y); \
    fma2(af[0], wf_, sv_.x); fma2(af[1], wf_, sv_.y); \
    fma2(ag[0], wg_, sv_.x); fma2(ag[1], wg_, sv_.y); \
    fma2(ao[0], wo_, sv_.x); fma2(ao[1], wo_, sv_.y); \
} while (0)

// Re-init accumulators from interleaved float4 bias array
#define ACC_INIT(BQOFF) do { \
    float4 bb_ = ((const float4*)(sm + (BQOFF)))[j]; \
    ai[0] = ai[1] = pack2(bb_.x, bb_.x); \
    af[0] = af[1] = pack2(bb_.y, bb_.y); \
    ag[0] = ag[1] = pack2(bb_.z, bb_.z); \
    ao[0] = ao[1] = pack2(bb_.w, bb_.w); \
} while (0)

// LSTM nonlinearity for this thread's 4 rows; consumes accs
#define EPILOGUE(LYR, HDST) do { \
    float hv_[4]; \
    _Pragma("unroll") \
    for (int p = 0; p < 2; p++) { \
        float2 vi_ = unpk(ai[p]), vf_ = unpk(af[p]); \
        float2 vg_ = unpk(ag[p]), vo_ = unpk(ao[p]); \
        float ncx_ = sig_a(vf_.x) * cx[LYR][p] + sig_a(vi_.x) * tanh_a(vg_.x); \
        float ncy_ = sig_a(vf_.y) * cy[LYR][p] + sig_a(vi_.y) * tanh_a(vg_.y); \
        cx[LYR][p] = ncx_; cy[LYR][p] = ncy_; \
        hv_[2*p]     = sig_a(vo_.x) * tanh_a(ncx_); \
        hv_[2*p + 1] = sig_a(vo_.y) * tanh_a(ncy_); \
    } \
    if (!dup) { \
        float4 q_; q_.x = hv_[0]; q_.y = hv_[1]; q_.z = hv_[2]; q_.w = hv_[3]; \
        *(float4*)&(HDST)[j * TSTRIDE + r0] = q_; \
    } \
} while (0)

__global__ __launch_bounds__(NTHREADS, 1)
void kozyra_lstm_kernel(const float* __restrict__ features,
                        const float* __restrict__ w_ih0, const float* __restrict__ w_hh0,
                        const float* __restrict__ b0,
                        const float* __restrict__ w_ih1, const float* __restrict__ w_hh1,
                        const float* __restrict__ b1,
                        const float* __restrict__ w_fc1, const float* __restrict__ b_fc1,
                        const float* __restrict__ w_fc2, const float* __restrict__ b_fc2,
                        float* __restrict__ out)
{
    extern __shared__ float sm[];
    float* s_fc1  = sm + OFF_FC1;
    float* s_fc2  = sm + OFF_FC2;
    float* s_bfc1 = sm + OFF_BFC1;
    float* s_bfc2 = sm + OFF_BFC2;
    float* s_x    = sm + OFF_X;      // [IN0][TSTRIDE], row 16 = delta
    float* s_h0b  = sm + OFF_H0;     // 2 x [HID][TSTRIDE]
    float* s_h1b  = sm + OFF_H1;

    const int tid  = threadIdx.x;
    const int brow = blockIdx.x * ROWS;

    // ---- Stage weights interleaved as float4 (wi,wf,wg,wo) per (j,k) ----
    for (int i = tid; i < HID * IN0 * 4; i += NTHREADS) {
        int gate = i & 3, rest = i >> 2;
        int jj = rest / IN0, k = rest % IN0;
        sm[OFF_W4_IH0 + (jj * W4I_S + k) * 4 + gate] = w_ih0[(gate * HID + jj) * IN0 + k];
    }
    for (int i = tid; i < HID * W4H_S * 4; i += NTHREADS) {
        int gate = i & 3, rest = i >> 2;
        int jj = rest / W4H_S, k = rest % W4H_S;
        float v0 = 0.0f, v1 = 0.0f, v2 = 0.0f;
        if (k < HID) {
            int src = (gate * HID + jj) * HID + k;
            v0 = w_hh0[src]; v1 = w_ih1[src]; v2 = w_hh1[src];
        }
        int o = (jj * W4H_S + k) * 4 + gate;
        sm[OFF_W4_HH0 + o] = v0;
        sm[OFF_W4_IH1 + o] = v1;
        sm[OFF_W4_HH1 + o] = v2;
    }
    for (int i = tid; i < FC1N * HID; i += NTHREADS) {
        int n = i / HID, k = i % HID;
        s_fc1[n * FC1_S + k] = w_fc1[i];
    }
    for (int i = tid; i < FC1N; i += NTHREADS) { s_fc2[i] = w_fc2[i]; s_bfc1[i] = b_fc1[i]; }
    for (int i = tid; i < NG; i += NTHREADS) {
        int gate = i / HID, jj = i % HID;
        sm[OFF_B0Q + jj * 4 + gate] = b0[i];
        sm[OFF_B1Q + jj * 4 + gate] = b1[i];
    }
    if (tid == 0) s_bfc2[0] = b_fc2[0];

    // ---- Init state + x for t=0 ----
    for (int i = tid; i < 2 * HID * TSTRIDE; i += NTHREADS) { s_h0b[i] = 0.0f; s_h1b[i] = 0.0f; }
    const float* fbase = features + (size_t)brow * (TSTEPS * SDIM);
    for (int i = tid; i < ROWS * SDIM; i += NTHREADS) {
        int r = i >> 4, s = i & 15;
        s_x[s * TSTRIDE + r] = fbase[(size_t)r * (TSTEPS * SDIM) + s];
    }
    if (tid < ROWS) s_x[SDIM * TSTRIDE + tid] = 0.0f;
    __syncthreads();   // last full-block barrier

    // ---- Thread mapping: half (13 warps, 32 rows); gs selects a 4-row subgroup ----
    const int w    = tid >> 5;
    const int lane = tid & 31;
    const int half = (w >= 13) ? 1 : 0;
    const int hw   = w - half * 13;
    const int gs   = lane >> 4;
    const int sub  = lane & 15;
    int rg, j; bool dup = false;
    if (hw < 12) { rg = hw / 3; j = (hw % 3) * 16 + sub; }
    else { j = 48 + (sub & 1); rg = (sub >> 1) & 3; dup = (sub >= 8); }
    const int hbase = half * HROWS;
    const int r0 = hbase + rg * 8 + gs * 4;   // this thread's 4 rows

    const float4* pW_ih0 = (const float4*)(sm + OFF_W4_IH0) + j * W4I_S;
    const float4* pW_hh0 = (const float4*)(sm + OFF_W4_HH0) + j * W4H_S;
    const float4* pW_ih1 = (const float4*)(sm + OFF_W4_IH1) + j * W4H_S;
    const float4* pW_hh1 = (const float4*)(sm + OFF_W4_HH1) + j * W4H_S;

    float cx[2][2], cy[2][2];
    cx[0][0]=cx[0][1]=cy[0][0]=cy[0][1]=0.0f;
    cx[1][0]=cx[1][1]=cy[1][0]=cy[1][1]=0.0f;

    // Pipelined accumulators (live across phases/barriers)
    ull ai[2], af[2], ag[2], ao[2];

    // ---- Prologue: L0 partial for t=0 (features only; h0(-1)=0, delta(-1)=0) ----
    ACC_INIT(OFF_B0Q);
    {
        const float* sx = &s_x[r0];
        #pragma unroll
        for (int k = 0; k < SDIM; k++) GATEK(pW_ih0, sx, k);
    }

    for (int t = 0; t < TSTEPS; t++) {
        const int pb = t & 1;
        float* h0w = s_h0b + (pb ^ 1) * (HID * TSTRIDE);   // h0(t) dest
        const float* h1r = s_h1b + pb * (HID * TSTRIDE);   // h1(t-1)
        float* h1w = s_h1b + (pb ^ 1) * (HID * TSTRIDE);   // h1(t) dest

        // ============ Phase 1: finish L0 (delta column) + epi0, overlapped
        //              with L1 partial (W_hh1 @ h1(t-1)) ============
        GATEK(pW_ih0, &s_x[r0], SDIM);     // delta column (k=16)
        {
            // epi0 consumes accs -> h0(t); then accs reinit for L1.
            // The W_hh1 GATEKs below are independent of epi0's MUFU chain;
            // ptxas interleaves them to hide the MUFU burst.
            float hv[4];
            #pragma unroll
            for (int p = 0; p < 2; p++) {
                float2 vi = unpk(ai[p]), vf = unpk(af[p]), vg = unpk(ag[p]), vo = unpk(ao[p]);
                float ncx = sig_a(vf.x) * cx[0][p] + sig_a(vi.x) * tanh_a(vg.x);
                float ncy = sig_a(vf.y) * cy[0][p] + sig_a(vi.y) * tanh_a(vg.y);
                cx[0][p] = ncx; cy[0][p] = ncy;
                hv[2*p]     = sig_a(vo.x) * tanh_a(ncx);
                hv[2*p + 1] = sig_a(vo.y) * tanh_a(ncy);
            }
            ACC_INIT(OFF_B1Q);
            {
                const float* sh = &h1r[r0];
                #pragma unroll 5
                for (int k = 0; k < HID; k++) GATEK(pW_hh1, sh, k);
            }
            if (!dup) {
                float4 q; q.x = hv[0]; q.y = hv[1]; q.z = hv[2]; q.w = hv[3];
                *(float4*)&h0w[j * TSTRIDE + r0] = q;
            }
        }
        half_bar(half);   // h0(t) visible

        // ============ Phase 2: finish L1 (W_ih1 @ h0(t)) + epi1, overlapped
        //              with L0 partial (first KSPLIT k's of W_hh0 @ h0(t))
        //              + x(t+1) prefetch ============
        const bool has_next = (t + 1 < TSTEPS);
        int hidx = hw * 32 + lane;
        float f0 = 0.0f, f1 = 0.0f;
        int rA = hidx >> 4, sA = hidx & 15;
        int hidx2 = hidx + HTHREADS;
        int rB = hidx2 >> 4, sB = hidx2 & 15;
        if (has_next) {   // issue gmem loads early; latency hidden by gate math
            f0 = fbase[(size_t)(hbase + rA) * (TSTEPS * SDIM) + (size_t)(t + 1) * SDIM + sA];
            if (rB < HROWS)
                f1 = fbase[(size_t)(hbase + rB) * (TSTEPS * SDIM) + (size_t)(t + 1) * SDIM + sB];
        }
        {
            const float* sh = &h0w[r0];
            #pragma unroll 5
            for (int k = 0; k < HID; k++) GATEK(pW_ih1, sh, k);
        }
        {
            float hv[4];
            #pragma unroll
            for (int p = 0; p < 2; p++) {
                float2 vi = unpk(ai[p]), vf = unpk(af[p]), vg = unpk(ag[p]), vo = unpk(ao[p]);
                float ncx = sig_a(vf.x) * cx[1][p] + sig_a(vi.x) * tanh_a(vg.x);
                float ncy = sig_a(vf.y) * cy[1][p] + sig_a(vi.y) * tanh_a(vg.y);
                cx[1][p] = ncx; cy[1][p] = ncy;
                hv[2*p]     = sig_a(vo.x) * tanh_a(ncx);
                hv[2*p + 1] = sig_a(vo.y) * tanh_a(ncy);
            }
            ACC_INIT(OFF_B0Q);
            {
                const float* sh = &h0w[r0];
                #pragma unroll 5
                for (int k = 0; k < KSPLIT; k++) GATEK(pW_hh0, sh, k);
            }
            if (!dup) {
                float4 q; q.x = hv[0]; q.y = hv[1]; q.z = hv[2]; q.w = hv[3];
                *(float4*)&h1w[j * TSTRIDE + r0] = q;
            }
        }
        if (has_next) {   // stage x(t+1) features (readers are past, bar'd)
            s_x[sA * TSTRIDE + hbase + rA] = f0;
            if (rB < HROWS)
                s_x[sB * TSTRIDE + hbase + rB] = f1;
        }
        half_bar(half);   // h1(t) + x(t+1) visible

        // ============ Phase 3: fc(t) overlapped with rest of L0 partial
        //              (W_hh0 k>=KSPLIT + W_ih0 @ x(t+1) features) ============
        ull acc0 = 0ULL, acc1 = 0ULL;
        if (hw < 8 && lane < FC1N) {   // fc dot-product (issued before partial)
            float bb1 = s_bfc1[lane];
            acc0 = pack2(bb1, bb1); acc1 = acc0;
            const float* wr = &s_fc1[lane * FC1_S];
            const int rb = hbase + hw * 4;
            #pragma unroll 10
            for (int k = 0; k < HID; k++) {
                float wv = wr[k];
                ull wp = pack2(wv, wv);
                ulonglong2 hv = *(const ulonglong2*)&h1w[k * TSTRIDE + rb];
                fma2(acc0, wp, hv.x);
                fma2(acc1, wp, hv.y);
            }
            float2 u0 = unpk(acc0), u1 = unpk(acc1);
            float sc = s_fc2[lane];
            u0.x = fmaxf(u0.x, 0.0f) * sc;  u0.y = fmaxf(u0.y, 0.0f) * sc;
            u1.x = fmaxf(u1.x, 0.0f) * sc;  u1.y = fmaxf(u1.y, 0.0f) * sc;
            acc0 = pack2(u0.x, u0.y); acc1 = pack2(u1.x, u1.y);
        }
        {
            const float* sh = &h0w[r0];
            #pragma unroll 5
            for (int k = KSPLIT; k < HID; k++) GATEK(pW_hh0, sh, k);
        }
        {
            const float* sx = &s_x[r0];
            #pragma unroll
            for (int k = 0; k < SDIM; k++) GATEK(pW_ih0, sx, k);
        }
        if (hw < 8) {   // fc reduce + delta/out write (inputs long ready)
            #pragma unroll
            for (int off = 16; off > 0; off >>= 1) {
                add2(acc0, __shfl_down_sync(0xffffffffu, acc0, off));
                add2(acc1, __shfl_down_sync(0xffffffffu, acc1, off));
            }
            if (lane == 0) {
                const int rb = hbase + hw * 4;
                float2 d0 = unpk(acc0), d1 = unpk(acc1);
                float bb = s_bfc2[0];
                d0.x += bb; d0.y += bb; d1.x += bb; d1.y += bb;
                float4 dd; dd.x = d0.x; dd.y = d0.y; dd.z = d1.x; dd.w = d1.y;
                *(float4*)&s_x[SDIM * TSTRIDE + rb] = dd;   // delta -> next x
                out[(size_t)(brow + rb)     * TSTEPS + t] = d0.x;
                out[(size_t)(brow + rb + 1) * TSTEPS + t] = d0.y;
                out[(size_t)(brow + rb + 2) * TSTEPS + t] = d1.x;
                out[(size_t)(brow + rb + 3) * TSTEPS + t] = d1.y;
            }
        }
        half_bar(half);   // delta visible; next Ph1 may finalize L0
    }
}

extern "C" void kernel_launch(void* const* d_in, const int* in_sizes, int n_in,
                              void* d_out, int out_size)
{
    const float* features = (const float*)d_in[0];
    const float* w_ih0    = (const float*)d_in[1];
    const float* w_hh0    = (const float*)d_in[2];
    const float* b0       = (const float*)d_in[3];
    const float* w_ih1    = (const float*)d_in[4];
    const float* w_hh1    = (const float*)d_in[5];
    const float* b1       = (const float*)d_in[6];
    const float* w_fc1    = (const float*)d_in[7];
    const float* b_fc1    = (const float*)d_in[8];
    const float* w_fc2    = (const float*)d_in[9];
    const float* b_fc2    = (const float*)d_in[10];
    float* out = (float*)d_out;

    const int batch = in_sizes[0] / (TSTEPS * SDIM);
    const int nblocks = batch / ROWS;

    const size_t smem_bytes = SMEM_FLOATS * sizeof(float);
    cudaFuncSetAttribute(kozyra_lstm_kernel,
                         cudaFuncAttributeMaxDynamicSharedMemorySize,
                         (int)smem_bytes);

    kozyra_lstm_kernel<<<nblocks, NTHREADS, smem_bytes>>>(
        features, w_ih0, w_hh0, b0, w_ih1, w_hh1, b1,
        w_fc1, b_fc1, w_fc2, b_fc2, out);
}

// round 14
// speedup vs baseline: 1.6442x; 1.0272x over previous
#include <cuda_runtime.h>

// Problem constants
#define HID     50
#define NG      200
#define IN0     17
#define SDIM    16
#define TSTEPS  128
#define FC1N    25

// Tiling: FOUR independent 16-row quarters, 7 warps each
#define ROWS      64
#define QROWS     16
#define NTHREADS  896
#define QTHREADS  224

// Strides
#define FC1_S     51
#define TSTRIDE   68      // floats; 272B rows, 16B-aligned
#define W4I_S     17      // wih0 float4 stride per j
#define W4H_S     51      // hh float4 stride per j

typedef unsigned long long ull;

__device__ __forceinline__ ull pack2(float a, float b) {
    ull r; asm("mov.b64 %0,{%1,%2};" : "=l"(r) : "f"(a), "f"(b)); return r;
}
__device__ __forceinline__ float2 unpk(ull v) {
    float2 f; asm("mov.b64 {%0,%1},%2;" : "=f"(f.x), "=f"(f.y) : "l"(v)); return f;
}
__device__ __forceinline__ void fma2(ull& d, ull a, ull b) {
    asm("fma.rn.f32x2 %0,%1,%2,%0;" : "+l"(d) : "l"(a), "l"(b));
}
__device__ __forceinline__ void add2(ull& d, ull a) {
    asm("add.rn.f32x2 %0,%0,%1;" : "+l"(d) : "l"(a));
}
__device__ __forceinline__ float tanh_a(float x) {
    float y; asm("tanh.approx.f32 %0,%1;" : "=f"(y) : "f"(x)); return y;
}
__device__ __forceinline__ float sig_a(float x) {
    return fmaf(tanh_a(0.5f * x), 0.5f, 0.5f);
}
__device__ __forceinline__ void quarter_bar(int q) {
    asm volatile("bar.sync %0, %1;" :: "r"(q + 1), "r"(QTHREADS) : "memory");
}

// Shared layout (float offsets; float4 regions 16B aligned)
#define OFF_W4_IH0 0         // 3400
#define OFF_W4_HH0 3400      // 10200
#define OFF_W4_IH1 13600     // 10200
#define OFF_W4_HH1 23800     // 10200
#define OFF_FC1    34000     // 1275
#define OFF_FC2    35276     // 25
#define OFF_B0     35302     // 200
#define OFF_B1     35502     // 200
#define OFF_BFC1   35702     // 25
#define OFF_BFC2   35728     // 2 (+2 pad)
#define OFF_X      35732     // 17*68 = 1156
#define OFF_H0     36888     // 2*50*68 = 6800
#define OFF_H1     43688     // 6800
#define SMEM_FLOATS 50488    // 201952 bytes

// One k of gate MACs: float4 weights (4 gates), one LDS.128 of state (4 rows)
#define GATEK(PW, SBASE, K) do { \
    float4 wv_ = (PW)[K]; \
    ull wi_ = pack2(wv_.x, wv_.x), wf_ = pack2(wv_.y, wv_.y); \
    ull wg_ = pack2(wv_.z, wv_.z), wo_ = pack2(wv_.w, wv_.w); \
    ulonglong2 sv_ = *(const ulonglong2*)((SBASE) + (K) * TSTRIDE); \
    fma2(ai[0], wi_, sv_.x); fma2(ai[1], wi_, sv_.y); \
    fma2(af[0], wf_, sv_.x); fma2(af[1], wf_, sv_.y); \
    fma2(ag[0], wg_, sv_.x); fma2(ag[1], wg_, sv_.y); \
    fma2(ao[0], wo_, sv_.x); fma2(ao[1], wo_, sv_.y); \
} while (0)

// LSTM nonlinearity for this thread's 4 rows (2 f32x2 pairs)
#define EPILOGUE(LYR, HDST) do { \
    float hv_[4]; \
    _Pragma("unroll") \
    for (int p = 0; p < 2; p++) { \
        float2 vi_ = unpk(ai[p]), vf_ = unpk(af[p]); \
        float2 vg_ = unpk(ag[p]), vo_ = unpk(ao[p]); \
        float ncx_ = sig_a(vf_.x) * cx[LYR][p] + sig_a(vi_.x) * tanh_a(vg_.x); \
        float ncy_ = sig_a(vf_.y) * cy[LYR][p] + sig_a(vi_.y) * tanh_a(vg_.y); \
        cx[LYR][p] = ncx_; cy[LYR][p] = ncy_; \
        hv_[2*p]     = sig_a(vo_.x) * tanh_a(ncx_); \
        hv_[2*p + 1] = sig_a(vo_.y) * tanh_a(ncy_); \
    } \
    if (!dup) { \
        float4 q_; q_.x = hv_[0]; q_.y = hv_[1]; q_.z = hv_[2]; q_.w = hv_[3]; \
        *(float4*)&(HDST)[j * TSTRIDE + r0] = q_; \
    } \
} while (0)

__global__ __launch_bounds__(NTHREADS, 1)
void kozyra_lstm_kernel(const float* __restrict__ features,
                        const float* __restrict__ w_ih0, const float* __restrict__ w_hh0,
                        const float* __restrict__ b0,
                        const float* __restrict__ w_ih1, const float* __restrict__ w_hh1,
                        const float* __restrict__ b1,
                        const float* __restrict__ w_fc1, const float* __restrict__ b_fc1,
                        const float* __restrict__ w_fc2, const float* __restrict__ b_fc2,
                        float* __restrict__ out)
{
    extern __shared__ float sm[];
    float* s_fc1  = sm + OFF_FC1;
    float* s_fc2  = sm + OFF_FC2;
    float* s_b0   = sm + OFF_B0;
    float* s_b1   = sm + OFF_B1;
    float* s_bfc1 = sm + OFF_BFC1;
    float* s_bfc2 = sm + OFF_BFC2;
    float* s_x    = sm + OFF_X;      // [IN0][TSTRIDE], row 16 = delta
    float* s_h0b  = sm + OFF_H0;     // 2 x [HID][TSTRIDE]
    float* s_h1b  = sm + OFF_H1;

    const int tid  = threadIdx.x;
    const int brow = blockIdx.x * ROWS;

    // ---- Stage weights interleaved as float4 (wi,wf,wg,wo) per (j,k) ----
    for (int i = tid; i < HID * IN0 * 4; i += NTHREADS) {
        int gate = i & 3, rest = i >> 2;
        int jj = rest / IN0, k = rest % IN0;
        sm[OFF_W4_IH0 + (jj * W4I_S + k) * 4 + gate] = w_ih0[(gate * HID + jj) * IN0 + k];
    }
    for (int i = tid; i < HID * W4H_S * 4; i += NTHREADS) {
        int gate = i & 3, rest = i >> 2;
        int jj = rest / W4H_S, k = rest % W4H_S;
        float v0 = 0.0f, v1 = 0.0f, v2 = 0.0f;
        if (k < HID) {
            int src = (gate * HID + jj) * HID + k;
            v0 = w_hh0[src]; v1 = w_ih1[src]; v2 = w_hh1[src];
        }
        int o = (jj * W4H_S + k) * 4 + gate;
        sm[OFF_W4_HH0 + o] = v0;
        sm[OFF_W4_IH1 + o] = v1;
        sm[OFF_W4_HH1 + o] = v2;
    }
    for (int i = tid; i < FC1N * HID; i += NTHREADS) {
        int n = i / HID, k = i % HID;
        s_fc1[n * FC1_S + k] = w_fc1[i];
    }
    for (int i = tid; i < FC1N; i += NTHREADS) { s_fc2[i] = w_fc2[i]; s_bfc1[i] = b_fc1[i]; }
    for (int i = tid; i < NG;   i += NTHREADS) { s_b0[i] = b0[i]; s_b1[i] = b1[i]; }
    if (tid == 0) s_bfc2[0] = b_fc2[0];

    // ---- Init state + x for t=0 ----
    for (int i = tid; i < 2 * HID * TSTRIDE; i += NTHREADS) { s_h0b[i] = 0.0f; s_h1b[i] = 0.0f; }
    const float* fbase = features + (size_t)brow * (TSTEPS * SDIM);
    for (int i = tid; i < ROWS * SDIM; i += NTHREADS) {
        int r = i >> 4, s = i & 15;
        s_x[s * TSTRIDE + r] = fbase[(size_t)r * (TSTEPS * SDIM) + s];
    }
    if (tid < ROWS) s_x[SDIM * TSTRIDE + tid] = 0.0f;
    __syncthreads();   // last full-block barrier

    // ---- Thread mapping: quarter (7 warps, 16 rows); gs selects 4-row subgroup ----
    const int w    = tid >> 5;
    const int lane = tid & 31;
    const int q    = w / 7;             // quarter 0..3
    const int hq   = w - q * 7;         // warp within quarter 0..6
    const int gs   = lane >> 4;
    const int sub  = lane & 15;
    int rg, j; bool dup = false;
    if (hq < 6) { rg = hq / 3; j = (hq % 3) * 16 + sub; }     // rg 0..1, j 0..47
    else { j = 48 + (sub & 1); rg = (sub >> 1) & 1; dup = (sub >= 4); }
    const int qbase = q * QROWS;
    const int r0 = qbase + rg * 8 + gs * 4;   // this thread's 4 rows

    const float4* pW_ih0 = (const float4*)(sm + OFF_W4_IH0) + j * W4I_S;
    const float4* pW_hh0 = (const float4*)(sm + OFF_W4_HH0) + j * W4H_S;
    const float4* pW_ih1 = (const float4*)(sm + OFF_W4_IH1) + j * W4H_S;
    const float4* pW_hh1 = (const float4*)(sm + OFF_W4_HH1) + j * W4H_S;

    // Bias packs (all 4 gates, both layers)
    const ull bi0 = pack2(s_b0[j], s_b0[j]);
    const ull bf0 = pack2(s_b0[HID + j], s_b0[HID + j]);
    const ull bg0 = pack2(s_b0[2*HID + j], s_b0[2*HID + j]);
    const ull bo0 = pack2(s_b0[3*HID + j], s_b0[3*HID + j]);
    const ull bi1 = pack2(s_b1[j], s_b1[j]);
    const ull bf1 = pack2(s_b1[HID + j], s_b1[HID + j]);
    const ull bg1 = pack2(s_b1[2*HID + j], s_b1[2*HID + j]);
    const ull bo1 = pack2(s_b1[3*HID + j], s_b1[3*HID + j]);

    float cx[2][2], cy[2][2];
    cx[0][0]=cx[0][1]=cy[0][0]=cy[0][1]=0.0f;
    cx[1][0]=cx[1][1]=cy[1][0]=cy[1][1]=0.0f;

    for (int t = 0; t < TSTEPS; t++) {
        const int pb = t & 1;
        const float* h0r = s_h0b + pb * (HID * TSTRIDE);
        float* h0w = s_h0b + (pb ^ 1) * (HID * TSTRIDE);
        const float* h1r = s_h1b + pb * (HID * TSTRIDE);
        float* h1w = s_h1b + (pb ^ 1) * (HID * TSTRIDE);

        ull ai[2], af[2], ag[2], ao[2];

        // ================= Layer 0 =================
        ai[0]=ai[1]=bi0; af[0]=af[1]=bf0; ag[0]=ag[1]=bg0; ao[0]=ao[1]=bo0;
        {
            const float* sx = &s_x[r0];
            #pragma unroll
            for (int k = 0; k < IN0; k++) GATEK(pW_ih0, sx, k);
        }
        {
            const float* sh = &h0r[r0];
            #pragma unroll 5
            for (int k = 0; k < HID; k++) GATEK(pW_hh0, sh, k);
        }
        EPILOGUE(0, h0w);
        quarter_bar(q);   // h0 rows of this quarter visible

        // ================= Layer 1 =================
        ai[0]=ai[1]=bi1; af[0]=af[1]=bf1; ag[0]=ag[1]=bg1; ao[0]=ao[1]=bo1;
        {
            const float* sh = &h0w[r0];
            #pragma unroll 5
            for (int k = 0; k < HID; k++) GATEK(pW_ih1, sh, k);
        }
        {
            const float* sh = &h1r[r0];
            #pragma unroll 5
            for (int k = 0; k < HID; k++) GATEK(pW_hh1, sh, k);
        }
        EPILOGUE(1, h1w);
        quarter_bar(q);   // h1 rows of this quarter visible

        // ========= fc1+fc2 fused (4 rows per warp, warps 0-3) + x for t+1 =========
        const bool has_next = (t + 1 < TSTEPS);
        // feature prefetch for this quarter's 16 rows (256 elems / 224 threads)
        int qidx = hq * 32 + lane;          // 0..223
        float f0 = 0.0f, f1 = 0.0f;
        int rA = qidx >> 4, sA = qidx & 15;            // rows 0..13
        int qidx2 = qidx + QTHREADS;
        int rB = qidx2 >> 4, sB = qidx2 & 15;          // rows 14..15 for qidx<32
        if (has_next) {
            f0 = fbase[(size_t)(qbase + rA) * (TSTEPS * SDIM) + (size_t)(t + 1) * SDIM + sA];
            if (rB < QROWS)
                f1 = fbase[(size_t)(qbase + rB) * (TSTEPS * SDIM) + (size_t)(t + 1) * SDIM + sB];
        }

        if (hq < 4) {
            int rb = qbase + hq * 4;
            ull acc0 = 0ULL, acc1 = 0ULL;
            if (lane < FC1N) {
                float bb1 = s_bfc1[lane];
                acc0 = pack2(bb1, bb1); acc1 = acc0;
                const float* wr = &s_fc1[lane * FC1_S];
                #pragma unroll 10
                for (int k = 0; k < HID; k++) {
                    float wv = wr[k];
                    ull wp = pack2(wv, wv);
                    ulonglong2 hv = *(const ulonglong2*)&h1w[k * TSTRIDE + rb];
                    fma2(acc0, wp, hv.x);
                    fma2(acc1, wp, hv.y);
                }
                float2 u0 = unpk(acc0), u1 = unpk(acc1);
                float sc = s_fc2[lane];
                u0.x = fmaxf(u0.x, 0.0f) * sc;  u0.y = fmaxf(u0.y, 0.0f) * sc;
                u1.x = fmaxf(u1.x, 0.0f) * sc;  u1.y = fmaxf(u1.y, 0.0f) * sc;
                acc0 = pack2(u0.x, u0.y); acc1 = pack2(u1.x, u1.y);
            }
            #pragma unroll
            for (int off = 16; off > 0; off >>= 1) {
                add2(acc0, __shfl_down_sync(0xffffffffu, acc0, off));
                add2(acc1, __shfl_down_sync(0xffffffffu, acc1, off));
            }
            if (lane == 0) {
                float2 d0 = unpk(acc0), d1 = unpk(acc1);
                float bb = s_bfc2[0];
                d0.x += bb; d0.y += bb; d1.x += bb; d1.y += bb;
                float4 dd; dd.x = d0.x; dd.y = d0.y; dd.z = d1.x; dd.w = d1.y;
                *(float4*)&s_x[SDIM * TSTRIDE + rb] = dd;   // delta -> next x
                out[(size_t)(brow + rb)     * TSTEPS + t] = d0.x;
                out[(size_t)(brow + rb + 1) * TSTEPS + t] = d0.y;
                out[(size_t)(brow + rb + 2) * TSTEPS + t] = d1.x;
                out[(size_t)(brow + rb + 3) * TSTEPS + t] = d1.y;
            }
        }

        // store prefetched features for t+1 (this quarter's rows)
        if (has_next) {
            s_x[sA * TSTRIDE + qbase + rA] = f0;
            if (rB < QROWS)
                s_x[sB * TSTRIDE + qbase + rB] = f1;
        }
        quarter_bar(q);   // delta + x(t+1) visible within quarter
    }
}

extern "C" void kernel_launch(void* const* d_in, const int* in_sizes, int n_in,
                              void* d_out, int out_size)
{
    const float* features = (const float*)d_in[0];
    const float* w_ih0    = (const float*)d_in[1];
    const float* w_hh0    = (const float*)d_in[2];
    const float* b0       = (const float*)d_in[3];
    const float* w_ih1    = (const float*)d_in[4];
    const float* w_hh1    = (const float*)d_in[5];
    const float* b1       = (const float*)d_in[6];
    const float* w_fc1    = (const float*)d_in[7];
    const float* b_fc1    = (const float*)d_in[8];
    const float* w_fc2    = (const float*)d_in[9];
    const float* b_fc2    = (const float*)d_in[10];
    float* out = (float*)d_out;

    const int batch = in_sizes[0] / (TSTEPS * SDIM);
    const int nblocks = batch / ROWS;

    const size_t smem_bytes = SMEM_FLOATS * sizeof(float);
    cudaFuncSetAttribute(kozyra_lstm_kernel,
                         cudaFuncAttributeMaxDynamicSharedMemorySize,
                         (int)smem_bytes);

    kozyra_lstm_kernel<<<nblocks, NTHREADS, smem_bytes>>>(
        features, w_ih0, w_hh0, b0, w_ih1, w_hh1, b1,
        w_fc1, b_fc1, w_fc2, b_fc2, out);
}

// round 15
// speedup vs baseline: 1.6442x; 1.0000x over previous
#include <cuda_runtime.h>

// Problem constants
#define HID     50
#define NG      200
#define IN0     17
#define SDIM    16
#define TSTEPS  128
#define FC1N    25

// Tiling: FOUR independent 16-row quarters, 7 warps each
#define ROWS      64
#define QROWS     16
#define NTHREADS  896
#define QTHREADS  224

// Strides
#define FC1_S     51
#define TSTRIDE   68      // floats; 272B rows, 16B-aligned
#define W4I_S     17      // wih0 float4 stride per j
#define W4H_S     51      // hh float4 stride per j (3j mod 8 = permutation -> conflict-free)

typedef unsigned long long ull;

__device__ __forceinline__ ull pack2(float a, float b) {
    ull r; asm("mov.b64 %0,{%1,%2};" : "=l"(r) : "f"(a), "f"(b)); return r;
}
__device__ __forceinline__ float2 unpk(ull v) {
    float2 f; asm("mov.b64 {%0,%1},%2;" : "=f"(f.x), "=f"(f.y) : "l"(v)); return f;
}
__device__ __forceinline__ void fma2(ull& d, ull a, ull b) {
    asm("fma.rn.f32x2 %0,%1,%2,%0;" : "+l"(d) : "l"(a), "l"(b));
}
__device__ __forceinline__ void add2(ull& d, ull a) {
    asm("add.rn.f32x2 %0,%0,%1;" : "+l"(d) : "l"(a));
}
__device__ __forceinline__ float tanh_a(float x) {
    float y; asm("tanh.approx.f32 %0,%1;" : "=f"(y) : "f"(x)); return y;
}
__device__ __forceinline__ float sig_a(float x) {
    return fmaf(tanh_a(0.5f * x), 0.5f, 0.5f);
}
__device__ __forceinline__ void quarter_bar(int q) {
    asm volatile("bar.sync %0, %1;" :: "r"(q + 1), "r"(QTHREADS) : "memory");
}

// Shared layout (float offsets; float4 regions 16B aligned)
#define OFF_W4_IH0 0         // 3400
#define OFF_W4_HH0 3400      // 10200
#define OFF_W4_IH1 13600     // 10200
#define OFF_W4_HH1 23800     // 10200
#define OFF_FC1    34000     // 1275
#define OFF_FC2    35276     // 25
#define OFF_B0     35302     // 200
#define OFF_B1     35502     // 200
#define OFF_BFC1   35702     // 25
#define OFF_BFC2   35728     // 2 (+2 pad)
#define OFF_X      35732     // 17*68 = 1156
#define OFF_H0     36888     // 2*50*68 = 6800
#define OFF_H1     43688     // 6800
#define SMEM_FLOATS 50488    // 201952 bytes

// One k of gate MACs: float4 weights (4 gates, 8 distinct j -> 1 wf),
// one LDS.128 of state (this lane's 4 rows; 4 slots broadcast -> 1 wf)
#define GATEK(PW, SBASE, K) do { \
    float4 wv_ = (PW)[K]; \
    ull wi_ = pack2(wv_.x, wv_.x), wf_ = pack2(wv_.y, wv_.y); \
    ull wg_ = pack2(wv_.z, wv_.z), wo_ = pack2(wv_.w, wv_.w); \
    ulonglong2 sv_ = *(const ulonglong2*)((SBASE) + (K) * TSTRIDE); \
    fma2(ai[0], wi_, sv_.x); fma2(ai[1], wi_, sv_.y); \
    fma2(af[0], wf_, sv_.x); fma2(af[1], wf_, sv_.y); \
    fma2(ag[0], wg_, sv_.x); fma2(ag[1], wg_, sv_.y); \
    fma2(ao[0], wo_, sv_.x); fma2(ao[1], wo_, sv_.y); \
} while (0)

// LSTM nonlinearity for this thread's 4 rows (2 f32x2 pairs)
#define EPILOGUE(LYR, HDST) do { \
    float hv_[4]; \
    _Pragma("unroll") \
    for (int p = 0; p < 2; p++) { \
        float2 vi_ = unpk(ai[p]), vf_ = unpk(af[p]); \
        float2 vg_ = unpk(ag[p]), vo_ = unpk(ao[p]); \
        float ncx_ = sig_a(vf_.x) * cx[LYR][p] + sig_a(vi_.x) * tanh_a(vg_.x); \
        float ncy_ = sig_a(vf_.y) * cy[LYR][p] + sig_a(vi_.y) * tanh_a(vg_.y); \
        cx[LYR][p] = ncx_; cy[LYR][p] = ncy_; \
        hv_[2*p]     = sig_a(vo_.x) * tanh_a(ncx_); \
        hv_[2*p + 1] = sig_a(vo_.y) * tanh_a(ncy_); \
    } \
    if (!dup) { \
        float4 q_; q_.x = hv_[0]; q_.y = hv_[1]; q_.z = hv_[2]; q_.w = hv_[3]; \
        *(float4*)&(HDST)[j * TSTRIDE + r0] = q_; \
    } \
} while (0)

__global__ __launch_bounds__(NTHREADS, 1)
void kozyra_lstm_kernel(const float* __restrict__ features,
                        const float* __restrict__ w_ih0, const float* __restrict__ w_hh0,
                        const float* __restrict__ b0,
                        const float* __restrict__ w_ih1, const float* __restrict__ w_hh1,
                        const float* __restrict__ b1,
                        const float* __restrict__ w_fc1, const float* __restrict__ b_fc1,
                        const float* __restrict__ w_fc2, const float* __restrict__ b_fc2,
                        float* __restrict__ out)
{
    extern __shared__ float sm[];
    float* s_fc1  = sm + OFF_FC1;
    float* s_fc2  = sm + OFF_FC2;
    float* s_b0   = sm + OFF_B0;
    float* s_b1   = sm + OFF_B1;
    float* s_bfc1 = sm + OFF_BFC1;
    float* s_bfc2 = sm + OFF_BFC2;
    float* s_x    = sm + OFF_X;      // [IN0][TSTRIDE], row 16 = delta
    float* s_h0b  = sm + OFF_H0;     // 2 x [HID][TSTRIDE]
    float* s_h1b  = sm + OFF_H1;

    const int tid  = threadIdx.x;
    const int brow = blockIdx.x * ROWS;

    // ---- Stage weights interleaved as float4 (wi,wf,wg,wo) per (j,k) ----
    for (int i = tid; i < HID * IN0 * 4; i += NTHREADS) {
        int gate = i & 3, rest = i >> 2;
        int jj = rest / IN0, k = rest % IN0;
        sm[OFF_W4_IH0 + (jj * W4I_S + k) * 4 + gate] = w_ih0[(gate * HID + jj) * IN0 + k];
    }
    for (int i = tid; i < HID * W4H_S * 4; i += NTHREADS) {
        int gate = i & 3, rest = i >> 2;
        int jj = rest / W4H_S, k = rest % W4H_S;
        float v0 = 0.0f, v1 = 0.0f, v2 = 0.0f;
        if (k < HID) {
            int src = (gate * HID + jj) * HID + k;
            v0 = w_hh0[src]; v1 = w_ih1[src]; v2 = w_hh1[src];
        }
        int o = (jj * W4H_S + k) * 4 + gate;
        sm[OFF_W4_HH0 + o] = v0;
        sm[OFF_W4_IH1 + o] = v1;
        sm[OFF_W4_HH1 + o] = v2;
    }
    for (int i = tid; i < FC1N * HID; i += NTHREADS) {
        int n = i / HID, k = i % HID;
        s_fc1[n * FC1_S + k] = w_fc1[i];
    }
    for (int i = tid; i < FC1N; i += NTHREADS) { s_fc2[i] = w_fc2[i]; s_bfc1[i] = b_fc1[i]; }
    for (int i = tid; i < NG;   i += NTHREADS) { s_b0[i] = b0[i]; s_b1[i] = b1[i]; }
    if (tid == 0) s_bfc2[0] = b_fc2[0];

    // ---- Init state + x for t=0 ----
    for (int i = tid; i < 2 * HID * TSTRIDE; i += NTHREADS) { s_h0b[i] = 0.0f; s_h1b[i] = 0.0f; }
    const float* fbase = features + (size_t)brow * (TSTEPS * SDIM);
    for (int i = tid; i < ROWS * SDIM; i += NTHREADS) {
        int r = i >> 4, s = i & 15;
        s_x[s * TSTRIDE + r] = fbase[(size_t)r * (TSTEPS * SDIM) + s];
    }
    if (tid < ROWS) s_x[SDIM * TSTRIDE + tid] = 0.0f;
    __syncthreads();   // last full-block barrier

    // ---- Thread mapping: quarter (7 warps, 16 rows); lane -> (j, 4-row quad) ----
    const int w    = tid >> 5;
    const int lane = tid & 31;
    const int q    = w / 7;             // quarter 0..3
    const int hq   = w - q * 7;         // warp within quarter 0..6
    int j, rq; bool dup = false;
    if (hq < 6) { j = hq * 8 + (lane & 7); rq = lane >> 3; }       // 8 j x 4 quads
    else { j = 48 + (lane & 1); rq = (lane >> 1) & 3; dup = (lane >= 8); }
    const int qbase = q * QROWS;
    const int r0 = qbase + rq * 4;      // this thread's 4 rows

    const float4* pW_ih0 = (const float4*)(sm + OFF_W4_IH0) + j * W4I_S;
    const float4* pW_hh0 = (const float4*)(sm + OFF_W4_HH0) + j * W4H_S;
    const float4* pW_ih1 = (const float4*)(sm + OFF_W4_IH1) + j * W4H_S;
    const float4* pW_hh1 = (const float4*)(sm + OFF_W4_HH1) + j * W4H_S;

    // Bias packs (all 4 gates, both layers)
    const ull bi0 = pack2(s_b0[j], s_b0[j]);
    const ull bf0 = pack2(s_b0[HID + j], s_b0[HID + j]);
    const ull bg0 = pack2(s_b0[2*HID + j], s_b0[2*HID + j]);
    const ull bo0 = pack2(s_b0[3*HID + j], s_b0[3*HID + j]);
    const ull bi1 = pack2(s_b1[j], s_b1[j]);
    const ull bf1 = pack2(s_b1[HID + j], s_b1[HID + j]);
    const ull bg1 = pack2(s_b1[2*HID + j], s_b1[2*HID + j]);
    const ull bo1 = pack2(s_b1[3*HID + j], s_b1[3*HID + j]);

    float cx[2][2], cy[2][2];
    cx[0][0]=cx[0][1]=cy[0][0]=cy[0][1]=0.0f;
    cx[1][0]=cx[1][1]=cy[1][0]=cy[1][1]=0.0f;

    for (int t = 0; t < TSTEPS; t++) {
        const int pb = t & 1;
        const float* h0r = s_h0b + pb * (HID * TSTRIDE);
        float* h0w = s_h0b + (pb ^ 1) * (HID * TSTRIDE);
        const float* h1r = s_h1b + pb * (HID * TSTRIDE);
        float* h1w = s_h1b + (pb ^ 1) * (HID * TSTRIDE);

        ull ai[2], af[2], ag[2], ao[2];

        // ================= Layer 0 =================
        ai[0]=ai[1]=bi0; af[0]=af[1]=bf0; ag[0]=ag[1]=bg0; ao[0]=ao[1]=bo0;
        {
            const float* sx = &s_x[r0];
            #pragma unroll
            for (int k = 0; k < IN0; k++) GATEK(pW_ih0, sx, k);
        }
        {
            const float* sh = &h0r[r0];
            #pragma unroll 5
            for (int k = 0; k < HID; k++) GATEK(pW_hh0, sh, k);
        }
        EPILOGUE(0, h0w);
        quarter_bar(q);   // h0 rows of this quarter visible

        // ================= Layer 1 =================
        ai[0]=ai[1]=bi1; af[0]=af[1]=bf1; ag[0]=ag[1]=bg1; ao[0]=ao[1]=bo1;
        {
            const float* sh = &h0w[r0];
            #pragma unroll 5
            for (int k = 0; k < HID; k++) GATEK(pW_ih1, sh, k);
        }
        {
            const float* sh = &h1r[r0];
            #pragma unroll 5
            for (int k = 0; k < HID; k++) GATEK(pW_hh1, sh, k);
        }
        EPILOGUE(1, h1w);
        quarter_bar(q);   // h1 rows of this quarter visible

        // ========= fc1+fc2 fused (4 rows per warp, warps 0-3) + x for t+1 =========
        const bool has_next = (t + 1 < TSTEPS);
        // feature prefetch for this quarter's 16 rows (256 elems / 224 threads)
        int qidx = hq * 32 + lane;          // 0..223
        float f0 = 0.0f, f1 = 0.0f;
        int rA = qidx >> 4, sA = qidx & 15;            // rows 0..13
        int qidx2 = qidx + QTHREADS;
        int rB = qidx2 >> 4, sB = qidx2 & 15;          // rows 14..15 for qidx<32
        if (has_next) {
            f0 = fbase[(size_t)(qbase + rA) * (TSTEPS * SDIM) + (size_t)(t + 1) * SDIM + sA];
            if (rB < QROWS)
                f1 = fbase[(size_t)(qbase + rB) * (TSTEPS * SDIM) + (size_t)(t + 1) * SDIM + sB];
        }

        if (hq < 4) {
            int rb = qbase + hq * 4;
            ull acc0 = 0ULL, acc1 = 0ULL;
            if (lane < FC1N) {
                float bb1 = s_bfc1[lane];
                acc0 = pack2(bb1, bb1); acc1 = acc0;
                const float* wr = &s_fc1[lane * FC1_S];
                #pragma unroll 10
                for (int k = 0; k < HID; k++) {
                    float wv = wr[k];
                    ull wp = pack2(wv, wv);
                    ulonglong2 hv = *(const ulonglong2*)&h1w[k * TSTRIDE + rb];
                    fma2(acc0, wp, hv.x);
                    fma2(acc1, wp, hv.y);
                }
                float2 u0 = unpk(acc0), u1 = unpk(acc1);
                float sc = s_fc2[lane];
                u0.x = fmaxf(u0.x, 0.0f) * sc;  u0.y = fmaxf(u0.y, 0.0f) * sc;
                u1.x = fmaxf(u1.x, 0.0f) * sc;  u1.y = fmaxf(u1.y, 0.0f) * sc;
                acc0 = pack2(u0.x, u0.y); acc1 = pack2(u1.x, u1.y);
            }
            #pragma unroll
            for (int off = 16; off > 0; off >>= 1) {
                add2(acc0, __shfl_down_sync(0xffffffffu, acc0, off));
                add2(acc1, __shfl_down_sync(0xffffffffu, acc1, off));
            }
            if (lane == 0) {
                float2 d0 = unpk(acc0), d1 = unpk(acc1);
                float bb = s_bfc2[0];
                d0.x += bb; d0.y += bb; d1.x += bb; d1.y += bb;
                float4 dd; dd.x = d0.x; dd.y = d0.y; dd.z = d1.x; dd.w = d1.y;
                *(float4*)&s_x[SDIM * TSTRIDE + rb] = dd;   // delta -> next x
                out[(size_t)(brow + rb)     * TSTEPS + t] = d0.x;
                out[(size_t)(brow + rb + 1) * TSTEPS + t] = d0.y;
                out[(size_t)(brow + rb + 2) * TSTEPS + t] = d1.x;
                out[(size_t)(brow + rb + 3) * TSTEPS + t] = d1.y;
            }
        }

        // store prefetched features for t+1 (this quarter's rows)
        if (has_next) {
            s_x[sA * TSTRIDE + qbase + rA] = f0;
            if (rB < QROWS)
                s_x[sB * TSTRIDE + qbase + rB] = f1;
        }
        quarter_bar(q);   // delta + x(t+1) visible within quarter
    }
}

extern "C" void kernel_launch(void* const* d_in, const int* in_sizes, int n_in,
                              void* d_out, int out_size)
{
    const float* features = (const float*)d_in[0];
    const float* w_ih0    = (const float*)d_in[1];
    const float* w_hh0    = (const float*)d_in[2];
    const float* b0       = (const float*)d_in[3];
    const float* w_ih1    = (const float*)d_in[4];
    const float* w_hh1    = (const float*)d_in[5];
    const float* b1       = (const float*)d_in[6];
    const float* w_fc1    = (const float*)d_in[7];
    const float* b_fc1    = (const float*)d_in[8];
    const float* w_fc2    = (const float*)d_in[9];
    const float* b_fc2    = (const float*)d_in[10];
    float* out = (float*)d_out;

    const int batch = in_sizes[0] / (TSTEPS * SDIM);
    const int nblocks = batch / ROWS;

    const size_t smem_bytes = SMEM_FLOATS * sizeof(float);
    cudaFuncSetAttribute(kozyra_lstm_kernel,
                         cudaFuncAttributeMaxDynamicSharedMemorySize,
                         (int)smem_bytes);

    kozyra_lstm_kernel<<<nblocks, NTHREADS, smem_bytes>>>(
        features, w_ih0, w_hh0, b0, w_ih1, w_hh1, b1,
        w_fc1, b_fc1, w_fc2, b_fc2, out);
}